// round 11
// baseline (speedup 1.0000x reference)
#include <cuda_runtime.h>
#include <cstdint>

// T=32768, H=1024, O=1024
//   scores[t] = enc[t,:] . w_enc  (softmax-invariant decoder term dropped)
//   weights   = softmax(scores)            -> d_out[1024 .. 1024+32768)
//   output[h] = sum_t weights[t]*enc[t,h]  -> d_out[0 .. 1024)
//
// pass1: 296 blocks = 2 CTAs/SM, each with its own 3-stage x 32KB
//   cp.async.bulk pipeline; each stage filled by 2x16KB bulk ops on one
//   mbarrier -> ~4 independent TMA requests in flight per SM (was 1).
//   Consumers: 1 row per warp per stage (R4 barrier discipline).
// finalize: proven split kernel.

#define T_ROWS    32768
#define HDIM      1024
#define NBLK      296
#define WARPS     8
#define NSTAGES   3
#define STG_ROWS  8
#define STG_F4    (STG_ROWS * 256)
#define STG_BYTES (STG_ROWS * HDIM * 4)      // 32768
#define NK        14                         // ceil(111/8)

__device__ float g_escore[T_ROWS];
__device__ float g_blk_s[NBLK];
__device__ float g_blk_acc[NBLK * HDIM];

__device__ __forceinline__ uint32_t smem_u32(const void* p) {
    return (uint32_t)__cvta_generic_to_shared(p);
}
__device__ __forceinline__ void mbar_init(uint32_t a, uint32_t cnt) {
    asm volatile("mbarrier.init.shared.b64 [%0], %1;" :: "r"(a), "r"(cnt) : "memory");
}
__device__ __forceinline__ void mbar_expect_tx(uint32_t a, uint32_t bytes) {
    asm volatile("mbarrier.arrive.expect_tx.shared.b64 _, [%0], %1;" :: "r"(a), "r"(bytes) : "memory");
}
__device__ __forceinline__ void mbar_arrive(uint32_t a) {
    asm volatile("mbarrier.arrive.shared.b64 _, [%0];" :: "r"(a) : "memory");
}
__device__ __forceinline__ void mbar_wait(uint32_t a, uint32_t parity) {
    uint32_t done;
    asm volatile(
        "{ .reg .pred p;\n"
        "  mbarrier.try_wait.parity.acquire.cta.shared::cta.b64 p, [%1], %2;\n"
        "  selp.b32 %0, 1, 0, p; }"
        : "=r"(done) : "r"(a), "r"(parity) : "memory");
    if (!done) {
        asm volatile(
            "{ .reg .pred P1;\n"
            "WL_%=:\n"
            "  mbarrier.try_wait.parity.acquire.cta.shared::cta.b64 P1, [%0], %1, 0x989680;\n"
            "  @P1 bra.uni WD_%=;\n"
            "  bra.uni WL_%=;\n"
            "WD_%=: }"
            :: "r"(a), "r"(parity) : "memory");
    }
}
__device__ __forceinline__ void bulk_g2s(uint32_t dst, const void* src,
                                         uint32_t bytes, uint32_t mbar) {
    asm volatile(
        "cp.async.bulk.shared::cluster.global.mbarrier::complete_tx::bytes [%0], [%1], %2, [%3];"
        :: "r"(dst), "l"(src), "r"(bytes), "r"(mbar) : "memory");
}

// fill one stage: 2 bulk ops (<=4 rows each) on the same barrier
__device__ __forceinline__ void fill_stage(uint32_t dst, const float* src,
                                           int rows, uint32_t mbar) {
    const int c0 = rows < 4 ? rows : 4;
    const int c1 = rows - c0;
    mbar_expect_tx(mbar, (uint32_t)rows * 4096u);
    bulk_g2s(dst, src, (uint32_t)c0 * 4096u, mbar);
    if (c1 > 0)
        bulk_g2s(dst + (uint32_t)c0 * 4096u, src + (size_t)c0 * HDIM,
                 (uint32_t)c1 * 4096u, mbar);
}

__global__ __launch_bounds__(256, 2)
void pass1_kernel(const float* __restrict__ enc, const float* __restrict__ attn_w)
{
    extern __shared__ __align__(16) float4 sbuf[];   // NSTAGES * STG_F4 = 96KB
    __shared__ __align__(16) float4 s_w[256];        // w_enc, 4KB
    __shared__ __align__(8) unsigned long long barr[2 * NSTAGES];
    __shared__ float sm_s[WARPS];

    const int tid  = threadIdx.x;
    const int lane = tid & 31;
    const int warp = tid >> 5;
    const int bid  = blockIdx.x;

    // 32768 = 296*110 + 208: blocks 0..207 get 111 rows, 208..295 get 110
    const int row_begin = bid * 110 + min(bid, 208);
    const int cnt = 110 + (bid < 208 ? 1 : 0);

    const uint32_t bar0 = smem_u32(barr);
#define FULLB(s)  (bar0 + (uint32_t)(s) * 8u)
#define EMPTYB(s) (bar0 + (uint32_t)((s) + NSTAGES) * 8u)
    const uint32_t stage0 = smem_u32(sbuf);

    if (tid == 0) {
        for (int i = 0; i < NSTAGES; i++) mbar_init(FULLB(i), 1);
        for (int i = 0; i < NSTAGES; i++) mbar_init(EMPTYB(i), 256);
    }
    // w_enc = attn_w[:, O:], O = 1024
    s_w[tid] = ((const float4*)(attn_w + 1024))[tid];
    asm volatile("fence.proxy.async.shared::cta;" ::: "memory");
    __syncthreads();

    // prologue: fill all stages
    if (tid == 0) {
#pragma unroll
        for (int k = 0; k < NSTAGES; k++) {
            const int rows = min(STG_ROWS, cnt - k * STG_ROWS);
            fill_stage(stage0 + k * STG_BYTES,
                       enc + (size_t)(row_begin + k * STG_ROWS) * HDIM,
                       rows, FULLB(k));
        }
    }

    float acc[32];
#pragma unroll
    for (int i = 0; i < 32; i++) acc[i] = 0.0f;
    float s = 0.0f;

    for (int k = 0; k < NK; k++) {
        const int st = k % NSTAGES;
        mbar_wait(FULLB(st), (uint32_t)((k / NSTAGES) & 1));

        const int rows = min(STG_ROWS, cnt - k * STG_ROWS);
        if (warp < rows) {
            const float4* __restrict__ base = sbuf + st * STG_F4 + warp * 256;

            float4 ev[8];
#pragma unroll
            for (int j = 0; j < 8; j++) ev[j] = base[j * 32 + lane];

            float da = 0.f, db = 0.f, dc = 0.f, dd = 0.f;
#pragma unroll
            for (int j = 0; j < 8; j++) {
                const float4 w = s_w[j * 32 + lane];
                da += ev[j].x * w.x;
                db += ev[j].y * w.y;
                dc += ev[j].z * w.z;
                dd += ev[j].w * w.w;
            }
            float d = (da + db) + (dc + dd);
#pragma unroll
            for (int o = 16; o > 0; o >>= 1)
                d += __shfl_xor_sync(0xffffffffu, d, o);

            const float w0 = __expf(d);
            if (lane == 0) g_escore[row_begin + k * STG_ROWS + warp] = w0;
            s += w0;
#pragma unroll
            for (int j = 0; j < 8; j++) {
                acc[4*j+0] += w0 * ev[j].x;
                acc[4*j+1] += w0 * ev[j].y;
                acc[4*j+2] += w0 * ev[j].z;
                acc[4*j+3] += w0 * ev[j].w;
            }
        }

        mbar_arrive(EMPTYB(st));   // all threads, after accumulate (R4 discipline)

        // refill this stage for round k+NSTAGES
        const int kn = k + NSTAGES;
        if (tid == 0 && kn < NK) {
            mbar_wait(EMPTYB(st), (uint32_t)(((kn / NSTAGES) - 1) & 1));
            const int rows2 = min(STG_ROWS, cnt - kn * STG_ROWS);
            if (rows2 > 0)
                fill_stage(stage0 + st * STG_BYTES,
                           enc + (size_t)(row_begin + kn * STG_ROWS) * HDIM,
                           rows2, FULLB(st));
            else
                mbar_expect_tx(FULLB(st), 0);   // keep phase sequence aligned
        }
    }

    // ---- block combine (reuse stage smem as scratch: 8x256 float4 = 32KB) ----
    __syncthreads();
    float4* sm_acc = sbuf;
    if (lane == 0) sm_s[warp] = s;
#pragma unroll
    for (int j = 0; j < 8; j++)
        sm_acc[warp * 256 + j * 32 + lane] =
            make_float4(acc[4*j+0], acc[4*j+1], acc[4*j+2], acc[4*j+3]);
    __syncthreads();

    float4 rsum = make_float4(0.f, 0.f, 0.f, 0.f);
#pragma unroll
    for (int w = 0; w < WARPS; w++) {
        const float4 a = sm_acc[w * 256 + tid];
        rsum.x += a.x; rsum.y += a.y; rsum.z += a.z; rsum.w += a.w;
    }
    ((float4*)g_blk_acc)[bid * 256 + tid] = rsum;

    if (tid == 0) {
        float S = 0.0f;
#pragma unroll
        for (int w = 0; w < WARPS; w++) S += sm_s[w];
        g_blk_s[bid] = S;
    }
}

// grid = 160 blocks x 256 threads.
//   blocks [0,128): weights  out[1024+t] = escore[t]*invS
//   blocks [128,160): output reduction over 296 partials; loads issued
//   before the invS chain so latency overlaps it.
__global__ __launch_bounds__(256)
void finalize_kernel(float* __restrict__ out)
{
    __shared__ float sws[8];
    __shared__ float sInv;
    __shared__ float sm2[8][32];

    const int tid  = threadIdx.x;
    const int lane = tid & 31;
    const int warp = tid >> 5;
    const int b    = blockIdx.x;

    // --- issue data loads first (independent of invS) ---
    float e = 0.0f, r = 0.0f;
    if (b < 128) {
        e = g_escore[b * 256 + tid];
    } else {
        const int d0 = (b - 128) * 32;
        const int dl = tid & 31;
        const int ch = tid >> 5;
#pragma unroll
        for (int w = 0; w < 37; w++) {           // 296 = 8*37
            const int idx = ch + 8 * w;
            r += g_blk_acc[idx * HDIM + d0 + dl];
        }
    }

    // --- invS reduction ---
    float v = g_blk_s[tid];
    if (tid < NBLK - 256) v += g_blk_s[tid + 256];
#pragma unroll
    for (int o = 16; o > 0; o >>= 1)
        v += __shfl_xor_sync(0xffffffffu, v, o);
    if (lane == 0) sws[warp] = v;
    __syncthreads();
    if (tid == 0) {
        float S = 0.0f;
#pragma unroll
        for (int j = 0; j < 8; j++) S += sws[j];
        sInv = 1.0f / S;
    }
    __syncthreads();
    const float invS = sInv;

    if (b < 128) {
        out[1024 + b * 256 + tid] = e * invS;
    } else {
        const int d0 = (b - 128) * 32;
        const int dl = tid & 31;
        const int ch = tid >> 5;
        sm2[ch][dl] = r;
        __syncthreads();
        if (ch == 0) {
            float t2 = 0.0f;
#pragma unroll
            for (int j = 0; j < 8; j++) t2 += sm2[j][dl];
            out[d0 + dl] = t2 * invS;
        }
    }
}

extern "C" void kernel_launch(void* const* d_in, const int* in_sizes, int n_in,
                              void* d_out, int out_size)
{
    // inputs: [0]=dec_h (unused), [1]=enc, [2]=attn_w, [3]=attn_b (unused)
    const float* enc    = (const float*)d_in[1];
    const float* attn_w = (const float*)d_in[2];
    float* out = (float*)d_out;

    cudaFuncSetAttribute(pass1_kernel,
                         cudaFuncAttributeMaxDynamicSharedMemorySize,
                         NSTAGES * STG_BYTES);
    pass1_kernel<<<NBLK, 256, NSTAGES * STG_BYTES>>>(enc, attn_w);
    finalize_kernel<<<160, 256>>>(out);
}

// round 12
// speedup vs baseline: 1.0620x; 1.0620x over previous
#include <cuda_runtime.h>
#include <cstdint>

// T=32768, H=1024, O=1024
//   scores[t] = enc[t,:] . w_enc  (softmax-invariant decoder term dropped)
//   weights   = softmax(scores)            -> d_out[1024 .. 1024+32768)
//   output[h] = sum_t weights[t]*enc[t,h]  -> d_out[0 .. 1024)
//
// pass1: WARP-PRIVATE TMA pipelines. Each warp owns 3 x 8KB buffers (2 rows)
//   + its own mbarriers. Refill for chunk k+3 is issued by lane0 right after
//   the warp's registers hold chunk k (__syncwarp only) -> no block-wide
//   barriers, 8 independent TMA streams/SM, ~128KB outstanding.
// finalize: split kernel launched with PDL (programmatic stream
//   serialization) to overlap its launch with pass1's tail.

#define T_ROWS    32768
#define HDIM      1024
#define NBLK      148
#define WARPS     8
#define NBUF      3
#define CHUNK_F4  512                        // 2 rows = 8KB = 512 float4
#define NK        14                         // 14 chunks x 2 rows = 28 rows/warp

__device__ float g_escore[T_ROWS];
__device__ float g_blk_s[NBLK];
__device__ float g_blk_acc[NBLK * HDIM];

__device__ __forceinline__ uint32_t smem_u32(const void* p) {
    return (uint32_t)__cvta_generic_to_shared(p);
}
__device__ __forceinline__ void mbar_init(uint32_t a, uint32_t cnt) {
    asm volatile("mbarrier.init.shared.b64 [%0], %1;" :: "r"(a), "r"(cnt) : "memory");
}
__device__ __forceinline__ void mbar_expect_tx(uint32_t a, uint32_t bytes) {
    asm volatile("mbarrier.arrive.expect_tx.shared.b64 _, [%0], %1;" :: "r"(a), "r"(bytes) : "memory");
}
__device__ __forceinline__ void mbar_wait(uint32_t a, uint32_t parity) {
    uint32_t done;
    asm volatile(
        "{ .reg .pred p;\n"
        "  mbarrier.try_wait.parity.acquire.cta.shared::cta.b64 p, [%1], %2;\n"
        "  selp.b32 %0, 1, 0, p; }"
        : "=r"(done) : "r"(a), "r"(parity) : "memory");
    if (!done) {
        asm volatile(
            "{ .reg .pred P1;\n"
            "WL_%=:\n"
            "  mbarrier.try_wait.parity.acquire.cta.shared::cta.b64 P1, [%0], %1, 0x989680;\n"
            "  @P1 bra.uni WD_%=;\n"
            "  bra.uni WL_%=;\n"
            "WD_%=: }"
            :: "r"(a), "r"(parity) : "memory");
    }
}
__device__ __forceinline__ void bulk_g2s(uint32_t dst, const void* src,
                                         uint32_t bytes, uint32_t mbar) {
    asm volatile(
        "cp.async.bulk.shared::cluster.global.mbarrier::complete_tx::bytes [%0], [%1], %2, [%3];"
        :: "r"(dst), "l"(src), "r"(bytes), "r"(mbar) : "memory");
}

__global__ __launch_bounds__(256, 1)
void pass1_kernel(const float* __restrict__ enc, const float* __restrict__ attn_w)
{
    extern __shared__ __align__(16) float4 sbuf[];   // 8 warps * 3 bufs * 512 f4 = 192KB
    __shared__ __align__(8) unsigned long long barr[WARPS * NBUF];
    __shared__ __align__(16) float4 s_w[256];        // w_enc, 4KB
    __shared__ float sm_s[WARPS];

    const int tid  = threadIdx.x;
    const int lane = tid & 31;
    const int warp = tid >> 5;
    const int bid  = blockIdx.x;

    // blocks 0..59: 222 rows, 60..147: 221 rows (total 32768)
    const int row_begin = bid * 221 + min(bid, 60);
    const int cnt = 221 + (bid < 60 ? 1 : 0);

    const uint32_t bar0 = smem_u32(barr);
#define WB(w, b) (bar0 + (uint32_t)((w) * NBUF + (b)) * 8u)
    const uint32_t stage0 = smem_u32(sbuf);
    const uint32_t wbase  = stage0 + (uint32_t)warp * NBUF * 8192u;

    if (tid < WARPS * NBUF) mbar_init(bar0 + tid * 8u, 1);
    s_w[tid] = ((const float4*)(attn_w + 1024))[tid];   // w_enc = attn_w[:,1024:]
    asm volatile("fence.proxy.async.shared::cta;" ::: "memory");
    __syncthreads();

    // chunk k of warp w covers block rows {16k+2w, 16k+2w+1}
    // (only chunk 13 can be partially/fully empty: 16*13+2*7=222)
    // prologue: fill bufs 0..2 (chunks 0..2 always have 2 rows)
    if (lane == 0) {
#pragma unroll
        for (int k = 0; k < NBUF; k++) {
            mbar_expect_tx(WB(warp, k), 8192u);
            bulk_g2s(wbase + (uint32_t)k * 8192u,
                     enc + (size_t)(row_begin + 16 * k + 2 * warp) * HDIM,
                     8192u, WB(warp, k));
        }
    }

    float acc[32];
#pragma unroll
    for (int i = 0; i < 32; i++) acc[i] = 0.0f;
    float s = 0.0f;

    for (int k = 0; k < NK; k++) {
        const int buf = k % NBUF;
        const int par = (k / NBUF) & 1;
        const int base = 16 * k + 2 * warp;
        int n = cnt - base; n = n < 0 ? 0 : (n > 2 ? 2 : n);

        float4 ev0[8], ev1[8];
        if (n > 0) {
            mbar_wait(WB(warp, buf), (uint32_t)par);
            const float4* __restrict__ bp = sbuf + (warp * NBUF + buf) * CHUNK_F4;
#pragma unroll
            for (int j = 0; j < 8; j++) ev0[j] = bp[j * 32 + lane];
            if (n == 2) {
#pragma unroll
                for (int j = 0; j < 8; j++) ev1[j] = bp[256 + j * 32 + lane];
            }
        }
        __syncwarp();

        // refill this buffer for chunk k+3 ASAP (warp-local, no block wait)
        const int kn = k + NBUF;
        if (lane == 0 && kn < NK) {
            const int basen = 16 * kn + 2 * warp;
            int nn = cnt - basen; nn = nn < 0 ? 0 : (nn > 2 ? 2 : nn);
            if (nn > 0) {
                mbar_expect_tx(WB(warp, buf), (uint32_t)nn * 4096u);
                bulk_g2s(wbase + (uint32_t)buf * 8192u,
                         enc + (size_t)(row_begin + basen) * HDIM,
                         (uint32_t)nn * 4096u, WB(warp, buf));
            }
        }

        if (n == 2) {
            float d0 = 0.0f, d1 = 0.0f;
#pragma unroll
            for (int j = 0; j < 8; j++) {
                const float4 w = s_w[j * 32 + lane];
                d0 += ev0[j].x * w.x; d0 += ev0[j].y * w.y;
                d0 += ev0[j].z * w.z; d0 += ev0[j].w * w.w;
                d1 += ev1[j].x * w.x; d1 += ev1[j].y * w.y;
                d1 += ev1[j].z * w.z; d1 += ev1[j].w * w.w;
            }
#pragma unroll
            for (int o = 16; o > 0; o >>= 1) {
                d0 += __shfl_xor_sync(0xffffffffu, d0, o);
                d1 += __shfl_xor_sync(0xffffffffu, d1, o);
            }
            const float w0 = __expf(d0);
            const float w1 = __expf(d1);
            if (lane == 0) {
                g_escore[row_begin + base]     = w0;
                g_escore[row_begin + base + 1] = w1;
            }
            s += w0 + w1;
#pragma unroll
            for (int j = 0; j < 8; j++) {
                acc[4*j+0] += w0 * ev0[j].x; acc[4*j+0] += w1 * ev1[j].x;
                acc[4*j+1] += w0 * ev0[j].y; acc[4*j+1] += w1 * ev1[j].y;
                acc[4*j+2] += w0 * ev0[j].z; acc[4*j+2] += w1 * ev1[j].z;
                acc[4*j+3] += w0 * ev0[j].w; acc[4*j+3] += w1 * ev1[j].w;
            }
        } else if (n == 1) {
            float d0 = 0.0f;
#pragma unroll
            for (int j = 0; j < 8; j++) {
                const float4 w = s_w[j * 32 + lane];
                d0 += ev0[j].x * w.x; d0 += ev0[j].y * w.y;
                d0 += ev0[j].z * w.z; d0 += ev0[j].w * w.w;
            }
#pragma unroll
            for (int o = 16; o > 0; o >>= 1)
                d0 += __shfl_xor_sync(0xffffffffu, d0, o);
            const float w0 = __expf(d0);
            if (lane == 0) g_escore[row_begin + base] = w0;
            s += w0;
#pragma unroll
            for (int j = 0; j < 8; j++) {
                acc[4*j+0] += w0 * ev0[j].x;
                acc[4*j+1] += w0 * ev0[j].y;
                acc[4*j+2] += w0 * ev0[j].z;
                acc[4*j+3] += w0 * ev0[j].w;
            }
        }
    }

    // ---- block combine (reuse warp-buffer smem as scratch) ----
    __syncthreads();
    float4* sm_acc = sbuf;                    // 8*256 float4 = 32KB
    if (lane == 0) sm_s[warp] = s;
#pragma unroll
    for (int j = 0; j < 8; j++)
        sm_acc[warp * 256 + j * 32 + lane] =
            make_float4(acc[4*j+0], acc[4*j+1], acc[4*j+2], acc[4*j+3]);
    __syncthreads();

    float4 rsum = make_float4(0.f, 0.f, 0.f, 0.f);
#pragma unroll
    for (int w = 0; w < WARPS; w++) {
        const float4 a = sm_acc[w * 256 + tid];
        rsum.x += a.x; rsum.y += a.y; rsum.z += a.z; rsum.w += a.w;
    }
    ((float4*)g_blk_acc)[bid * 256 + tid] = rsum;

    if (tid == 0) {
        float S = 0.0f;
#pragma unroll
        for (int w = 0; w < WARPS; w++) S += sm_s[w];
        g_blk_s[bid] = S;
    }

    // let the PDL-gated finalize kernel begin launching
    cudaTriggerProgrammaticLaunchCompletion();
}

// grid = 160 blocks x 256 threads (PDL secondary).
//   blocks [0,128): weights  out[1024+t] = escore[t]*invS
//   blocks [128,160): output reduction over 148 partials.
__global__ __launch_bounds__(256)
void finalize_kernel(float* __restrict__ out)
{
    __shared__ float sws[8];
    __shared__ float sInv;
    __shared__ float sm2[8][32];

    const int tid  = threadIdx.x;
    const int lane = tid & 31;
    const int warp = tid >> 5;
    const int b    = blockIdx.x;

    // wait until pass1's writes are visible (PDL)
    cudaGridDependencySynchronize();

    // --- issue data loads first (independent of invS) ---
    float e = 0.0f, r = 0.0f;
    if (b < 128) {
        e = g_escore[b * 256 + tid];
    } else {
        const int d0 = (b - 128) * 32;
        const int dl = tid & 31;
        const int ch = tid >> 5;
#pragma unroll
        for (int w = 0; w < 19; w++) {           // ch + 8*w < 148
            const int idx = ch + 8 * w;
            if (idx < NBLK) r += g_blk_acc[idx * HDIM + d0 + dl];
        }
    }

    // --- invS reduction ---
    float v = (tid < NBLK) ? g_blk_s[tid] : 0.0f;
#pragma unroll
    for (int o = 16; o > 0; o >>= 1)
        v += __shfl_xor_sync(0xffffffffu, v, o);
    if (lane == 0) sws[warp] = v;
    __syncthreads();
    if (tid == 0) {
        float S = 0.0f;
#pragma unroll
        for (int j = 0; j < 8; j++) S += sws[j];
        sInv = 1.0f / S;
    }
    __syncthreads();
    const float invS = sInv;

    if (b < 128) {
        out[1024 + b * 256 + tid] = e * invS;
    } else {
        const int d0 = (b - 128) * 32;
        const int dl = tid & 31;
        const int ch = tid >> 5;
        sm2[ch][dl] = r;
        __syncthreads();
        if (ch == 0) {
            float t2 = 0.0f;
#pragma unroll
            for (int j = 0; j < 8; j++) t2 += sm2[j][dl];
            out[d0 + dl] = t2 * invS;
        }
    }
}

extern "C" void kernel_launch(void* const* d_in, const int* in_sizes, int n_in,
                              void* d_out, int out_size)
{
    // inputs: [0]=dec_h (unused), [1]=enc, [2]=attn_w, [3]=attn_b (unused)
    const float* enc    = (const float*)d_in[1];
    const float* attn_w = (const float*)d_in[2];
    float* out = (float*)d_out;

    cudaFuncSetAttribute(pass1_kernel,
                         cudaFuncAttributeMaxDynamicSharedMemorySize,
                         WARPS * NBUF * 8192);
    pass1_kernel<<<NBLK, 256, WARPS * NBUF * 8192>>>(enc, attn_w);

    // finalize with programmatic dependent launch (overlaps launch with
    // pass1's tail; cudaGridDependencySynchronize gates data reads)
    cudaLaunchConfig_t cfg = {};
    cfg.gridDim  = dim3(160, 1, 1);
    cfg.blockDim = dim3(256, 1, 1);
    cfg.dynamicSmemBytes = 0;
    cfg.stream = 0;
    cudaLaunchAttribute attr[1];
    attr[0].id = cudaLaunchAttributeProgrammaticStreamSerialization;
    attr[0].val.programmaticStreamSerializationAllowed = 1;
    cfg.attrs = attr;
    cfg.numAttrs = 1;
    cudaLaunchKernelEx(&cfg, finalize_kernel, out);
}

// round 13
// speedup vs baseline: 1.0892x; 1.0256x over previous
#include <cuda_runtime.h>
#include <cstdint>

// T=32768, H=1024, O=1024
//   scores[t] = enc[t,:] . w_enc  (softmax-invariant decoder term dropped)
//   weights   = softmax(scores)            -> d_out[1024 .. 1024+32768)
//   output[h] = sum_t weights[t]*enc[t,h]  -> d_out[0 .. 1024)
//
// pass1: R4 structure VERBATIM (best measured wall time): 3-stage x 64KB
//   cp.async.bulk pipeline, 2-row-per-warp consumers, block-wide barriers.
// finalize: PDL secondary (launch overlaps pass1 tail), 96 blocks:
//   64 blocks write weights as float4, 32 blocks reduce the output dims.

#define T_ROWS     32768
#define HDIM       1024
#define NBLK1      148
#define NSTAGES    3
#define STG_ROWS   16
#define STG_F4     (STG_ROWS * 256)
#define STG_BYTES  (STG_ROWS * HDIM * 4)     // 65536
#define NK         14                        // ceil(222/16)

__device__ float g_escore[T_ROWS];
__device__ float g_blk_s[NBLK1];
__device__ float g_blk_acc[NBLK1 * HDIM];

__device__ __forceinline__ uint32_t smem_u32(const void* p) {
    return (uint32_t)__cvta_generic_to_shared(p);
}
__device__ __forceinline__ void mbar_init(uint32_t a, uint32_t cnt) {
    asm volatile("mbarrier.init.shared.b64 [%0], %1;" :: "r"(a), "r"(cnt) : "memory");
}
__device__ __forceinline__ void mbar_expect_tx(uint32_t a, uint32_t bytes) {
    asm volatile("mbarrier.arrive.expect_tx.shared.b64 _, [%0], %1;" :: "r"(a), "r"(bytes) : "memory");
}
__device__ __forceinline__ void mbar_arrive(uint32_t a) {
    asm volatile("mbarrier.arrive.shared.b64 _, [%0];" :: "r"(a) : "memory");
}
__device__ __forceinline__ void mbar_wait(uint32_t a, uint32_t parity) {
    uint32_t done;
    asm volatile(
        "{ .reg .pred p;\n"
        "  mbarrier.try_wait.parity.acquire.cta.shared::cta.b64 p, [%1], %2;\n"
        "  selp.b32 %0, 1, 0, p; }"
        : "=r"(done) : "r"(a), "r"(parity) : "memory");
    if (!done) {
        asm volatile(
            "{ .reg .pred P1;\n"
            "WL_%=:\n"
            "  mbarrier.try_wait.parity.acquire.cta.shared::cta.b64 P1, [%0], %1, 0x989680;\n"
            "  @P1 bra.uni WD_%=;\n"
            "  bra.uni WL_%=;\n"
            "WD_%=: }"
            :: "r"(a), "r"(parity) : "memory");
    }
}
__device__ __forceinline__ void bulk_g2s(uint32_t dst, const void* src,
                                         uint32_t bytes, uint32_t mbar) {
    asm volatile(
        "cp.async.bulk.shared::cluster.global.mbarrier::complete_tx::bytes [%0], [%1], %2, [%3];"
        :: "r"(dst), "l"(src), "r"(bytes), "r"(mbar) : "memory");
}

__global__ __launch_bounds__(256, 1)
void pass1_kernel(const float* __restrict__ enc, const float* __restrict__ attn_w)
{
    extern __shared__ __align__(16) float4 sbuf[];   // NSTAGES * STG_F4
    __shared__ __align__(8) unsigned long long barr[2 * NSTAGES];
    __shared__ float sm_s[8];

    const int tid  = threadIdx.x;
    const int lane = tid & 31;
    const int warp = tid >> 5;
    const int bid  = blockIdx.x;

    // blocks 0..59: 222 rows, 60..147: 221 rows (total 32768)
    const int row_begin = bid * 221 + min(bid, 60);
    const int cnt = 221 + (bid < 60 ? 1 : 0);

    const uint32_t bar0 = smem_u32(barr);
#define FULLB(s)  (bar0 + (uint32_t)(s) * 8u)
#define EMPTYB(s) (bar0 + (uint32_t)((s) + NSTAGES) * 8u)
    const uint32_t stage0 = smem_u32(sbuf);

    if (tid == 0) {
        for (int i = 0; i < NSTAGES; i++) mbar_init(FULLB(i), 1);
        for (int i = 0; i < NSTAGES; i++) mbar_init(EMPTYB(i), 256);
    }
    asm volatile("fence.proxy.async.shared::cta;" ::: "memory");
    __syncthreads();

    // prologue: fill all stages
    if (tid == 0) {
#pragma unroll
        for (int k = 0; k < NSTAGES; k++) {
            const int rows = min(STG_ROWS, cnt - k * STG_ROWS);
            const uint32_t bytes = (uint32_t)rows * HDIM * 4u;
            mbar_expect_tx(FULLB(k), bytes);
            bulk_g2s(stage0 + k * STG_BYTES,
                     enc + (size_t)(row_begin + k * STG_ROWS) * HDIM,
                     bytes, FULLB(k));
        }
    }

    // w_enc = attn_w[:, 1024:]
    float4 wv[8];
    {
        const float4* __restrict__ w4 = (const float4*)(attn_w + 1024);
#pragma unroll
        for (int k = 0; k < 8; k++) wv[k] = w4[k * 32 + lane];
    }

    float acc[32];
#pragma unroll
    for (int i = 0; i < 32; i++) acc[i] = 0.0f;
    float s = 0.0f;

    for (int k = 0; k < NK; k++) {
        const int st = k % NSTAGES;
        mbar_wait(FULLB(st), (uint32_t)((k / NSTAGES) & 1));

        const int rows = min(STG_ROWS, cnt - k * STG_ROWS);
        const int rr = 2 * warp;
        const float4* __restrict__ base = sbuf + st * STG_F4 + rr * 256;

        if (rr + 1 < rows) {
            float4 ev0[8], ev1[8];
#pragma unroll
            for (int j = 0; j < 8; j++) ev0[j] = base[j * 32 + lane];
#pragma unroll
            for (int j = 0; j < 8; j++) ev1[j] = base[256 + j * 32 + lane];

            float d0 = 0.0f, d1 = 0.0f;
#pragma unroll
            for (int j = 0; j < 8; j++) {
                d0 += ev0[j].x * wv[j].x; d0 += ev0[j].y * wv[j].y;
                d0 += ev0[j].z * wv[j].z; d0 += ev0[j].w * wv[j].w;
                d1 += ev1[j].x * wv[j].x; d1 += ev1[j].y * wv[j].y;
                d1 += ev1[j].z * wv[j].z; d1 += ev1[j].w * wv[j].w;
            }
#pragma unroll
            for (int o = 16; o > 0; o >>= 1) {
                d0 += __shfl_xor_sync(0xffffffffu, d0, o);
                d1 += __shfl_xor_sync(0xffffffffu, d1, o);
            }
            const float w0 = __expf(d0);
            const float w1 = __expf(d1);
            const int grow = row_begin + k * STG_ROWS + rr;
            if (lane == 0) {
                g_escore[grow]     = w0;
                g_escore[grow + 1] = w1;
            }
            s += w0 + w1;
#pragma unroll
            for (int j = 0; j < 8; j++) {
                acc[4*j+0] += w0 * ev0[j].x; acc[4*j+0] += w1 * ev1[j].x;
                acc[4*j+1] += w0 * ev0[j].y; acc[4*j+1] += w1 * ev1[j].y;
                acc[4*j+2] += w0 * ev0[j].z; acc[4*j+2] += w1 * ev1[j].z;
                acc[4*j+3] += w0 * ev0[j].w; acc[4*j+3] += w1 * ev1[j].w;
            }
        } else if (rr < rows) {
            float4 ev0[8];
#pragma unroll
            for (int j = 0; j < 8; j++) ev0[j] = base[j * 32 + lane];
            float d0 = 0.0f;
#pragma unroll
            for (int j = 0; j < 8; j++) {
                d0 += ev0[j].x * wv[j].x; d0 += ev0[j].y * wv[j].y;
                d0 += ev0[j].z * wv[j].z; d0 += ev0[j].w * wv[j].w;
            }
#pragma unroll
            for (int o = 16; o > 0; o >>= 1)
                d0 += __shfl_xor_sync(0xffffffffu, d0, o);
            const float w0 = __expf(d0);
            if (lane == 0) g_escore[row_begin + k * STG_ROWS + rr] = w0;
            s += w0;
#pragma unroll
            for (int j = 0; j < 8; j++) {
                acc[4*j+0] += w0 * ev0[j].x;
                acc[4*j+1] += w0 * ev0[j].y;
                acc[4*j+2] += w0 * ev0[j].z;
                acc[4*j+3] += w0 * ev0[j].w;
            }
        }

        mbar_arrive(EMPTYB(st));   // all 256 threads, after accumulate

        // refill this stage for round k+NSTAGES
        const int kn = k + NSTAGES;
        if (tid == 0 && kn < NK) {
            mbar_wait(EMPTYB(st), (uint32_t)(((kn / NSTAGES) - 1) & 1));
            const int rows2 = min(STG_ROWS, cnt - kn * STG_ROWS);
            const uint32_t bytes = (uint32_t)rows2 * HDIM * 4u;
            mbar_expect_tx(FULLB(st), bytes);
            bulk_g2s(stage0 + st * STG_BYTES,
                     enc + (size_t)(row_begin + kn * STG_ROWS) * HDIM,
                     bytes, FULLB(st));
        }
    }

    // ---- block combine (reuse stage smem as scratch) ----
    __syncthreads();
    float4* sm_acc = sbuf;                    // 8*256 float4 = 32KB
    if (lane == 0) sm_s[warp] = s;
#pragma unroll
    for (int j = 0; j < 8; j++)
        sm_acc[warp * 256 + j * 32 + lane] =
            make_float4(acc[4*j+0], acc[4*j+1], acc[4*j+2], acc[4*j+3]);
    __syncthreads();

    float4 rsum = make_float4(0.f, 0.f, 0.f, 0.f);
#pragma unroll
    for (int w = 0; w < 8; w++) {
        const float4 a = sm_acc[w * 256 + tid];
        rsum.x += a.x; rsum.y += a.y; rsum.z += a.z; rsum.w += a.w;
    }
    ((float4*)g_blk_acc)[bid * 256 + tid] = rsum;

    if (tid == 0) {
        float S = 0.0f;
#pragma unroll
        for (int w = 0; w < 8; w++) S += sm_s[w];
        g_blk_s[bid] = S;
    }

    // allow the PDL-gated finalize to begin its launch
    cudaTriggerProgrammaticLaunchCompletion();
}

// PDL secondary: 96 blocks x 256 threads.
//   blocks [0,64): weights as float4 (each thread one float4 of 4 rows)
//   blocks [64,96): output reduction over 148 partials (32 dims/block)
__global__ __launch_bounds__(256)
void finalize_kernel(float* __restrict__ out)
{
    __shared__ float sws[8];
    __shared__ float sInv;
    __shared__ float sm2[8][32];

    const int tid  = threadIdx.x;
    const int lane = tid & 31;
    const int warp = tid >> 5;
    const int b    = blockIdx.x;

    cudaGridDependencySynchronize();   // pass1 writes visible after this

    // --- issue data loads first (independent of invS chain) ---
    float4 e4 = make_float4(0.f, 0.f, 0.f, 0.f);
    float r = 0.0f;
    if (b < 64) {
        e4 = ((const float4*)g_escore)[b * 256 + tid];
    } else {
        const int d0 = (b - 64) * 32;
        const int dl = tid & 31;
        const int ch = tid >> 5;
#pragma unroll
        for (int w = 0; w < 19; w++) {           // ch + 8*w < 148
            const int idx = ch + 8 * w;
            if (idx < NBLK1) r += g_blk_acc[idx * HDIM + d0 + dl];
        }
    }

    // --- invS reduction (warp shuffle + 1 barrier round) ---
    float v = (tid < NBLK1) ? g_blk_s[tid] : 0.0f;
#pragma unroll
    for (int o = 16; o > 0; o >>= 1)
        v += __shfl_xor_sync(0xffffffffu, v, o);
    if (lane == 0) sws[warp] = v;
    __syncthreads();
    if (tid == 0) {
        float S = 0.0f;
#pragma unroll
        for (int j = 0; j < 8; j++) S += sws[j];
        sInv = 1.0f / S;
    }
    __syncthreads();
    const float invS = sInv;

    if (b < 64) {
        e4.x *= invS; e4.y *= invS; e4.z *= invS; e4.w *= invS;
        ((float4*)(out + 1024))[b * 256 + tid] = e4;
    } else {
        const int d0 = (b - 64) * 32;
        const int dl = tid & 31;
        const int ch = tid >> 5;
        sm2[ch][dl] = r;
        __syncthreads();
        if (ch == 0) {
            float t2 = 0.0f;
#pragma unroll
            for (int j = 0; j < 8; j++) t2 += sm2[j][dl];
            out[d0 + dl] = t2 * invS;
        }
    }
}

extern "C" void kernel_launch(void* const* d_in, const int* in_sizes, int n_in,
                              void* d_out, int out_size)
{
    // inputs: [0]=dec_h (unused), [1]=enc, [2]=attn_w, [3]=attn_b (unused)
    const float* enc    = (const float*)d_in[1];
    const float* attn_w = (const float*)d_in[2];
    float* out = (float*)d_out;

    cudaFuncSetAttribute(pass1_kernel,
                         cudaFuncAttributeMaxDynamicSharedMemorySize,
                         NSTAGES * STG_BYTES);
    pass1_kernel<<<NBLK1, 256, NSTAGES * STG_BYTES>>>(enc, attn_w);

    // finalize with programmatic dependent launch: launch overlaps pass1's
    // tail; cudaGridDependencySynchronize gates the data reads.
    cudaLaunchConfig_t cfg = {};
    cfg.gridDim  = dim3(96, 1, 1);
    cfg.blockDim = dim3(256, 1, 1);
    cfg.dynamicSmemBytes = 0;
    cfg.stream = 0;
    cudaLaunchAttribute attr[1];
    attr[0].id = cudaLaunchAttributeProgrammaticStreamSerialization;
    attr[0].val.programmaticStreamSerializationAllowed = 1;
    cfg.attrs = attr;
    cfg.numAttrs = 1;
    cudaLaunchKernelEx(&cfg, finalize_kernel, out);
}